// round 15
// baseline (speedup 1.0000x reference)
#include <cuda_runtime.h>
#include <math.h>
#include <cstdint>

#define TOTAL 4608
#define DMODEL 768
#define DFF 3072

// -------- scratch --------
__device__ uint32_t g_xnb  [TOTAL * 384];
__device__ float    g_qkv  [TOTAL * 2304];
__device__ uint32_t g_attnb[TOTAL * 384];
__device__ float    g_x1   [TOTAL * 768];
__device__ uint32_t g_hb   [TOTAL * 1536];
__device__ uint32_t g_wq   [884736];
__device__ uint32_t g_wp   [294912];
__device__ uint32_t g_w1   [1179648];
__device__ uint32_t g_w2   [1179648];

__constant__ int c_cu[9]    = {0, 1024, 1920, 2688, 3328, 3840, 4288, 4544, 4608};
__constant__ int c_pfx64[9] = {0, 16, 30, 42, 52, 60, 67, 71, 72};  // prefix of ceil(L/64)

__device__ __forceinline__ uint32_t smem_u32(const void* p) {
    uint32_t a;
    asm("{ .reg .u64 t; cvta.to.shared.u64 t, %1; cvt.u32.u64 %0, t; }" : "=r"(a) : "l"(p));
    return a;
}
__device__ __forceinline__ uint32_t pack_bf16x2(float lo, float hi) {
    uint32_t u;
    asm("cvt.rn.bf16x2.f32 %0, %1, %2;" : "=r"(u) : "f"(hi), "f"(lo));
    return u;
}
__device__ __forceinline__ uint16_t f2bf16(float v) {
    uint16_t h;
    asm("cvt.rn.bf16.f32 %0, %1;" : "=h"(h) : "f"(v));
    return h;
}
__device__ __forceinline__ float fexp2nc(float t) {
    float n = rintf(t);
    float f = t - n;
    float p = 8.98934e-3f;
    p = fmaf(p, f, 5.58263e-2f);
    p = fmaf(p, f, 2.40153e-1f);
    p = fmaf(p, f, 6.93147e-1f);
    p = fmaf(p, f, 1.0f);
    return __int_as_float(__float_as_int(p) + (((int)n) << 23));
}

#define MMA_BF16(d0,d1,d2,d3,a0,a1,a2,a3,b0,b1) \
    asm volatile("mma.sync.aligned.m16n8k16.row.col.f32.bf16.bf16.f32 " \
        "{%0,%1,%2,%3}, {%4,%5,%6,%7}, {%8,%9}, {%0,%1,%2,%3};" \
        : "+f"(d0), "+f"(d1), "+f"(d2), "+f"(d3) \
        : "r"(a0), "r"(a1), "r"(a2), "r"(a3), "r"(b0), "r"(b1))

#define CP16(dst, src) \
    asm volatile("cp.async.cg.shared.global [%0], [%1], 16;" :: "r"(dst), "l"(src))
#define CP_COMMIT() asm volatile("cp.async.commit_group;" ::: "memory")
#define CP_WAIT1()  asm volatile("cp.async.wait_group 1;" ::: "memory")
#define CP_WAIT0()  asm volatile("cp.async.wait_group 0;" ::: "memory")

// ---------------- f32 -> bf16x2 convert ----------------
__global__ __launch_bounds__(256) void cvt_bf16(const float* __restrict__ src,
                                                uint32_t* __restrict__ dst, int n4) {
    int i = blockIdx.x * 256 + threadIdx.x;
    if (i < n4) {
        float4 v = ((const float4*)src)[i];
        ((uint2*)dst)[i] = make_uint2(pack_bf16x2(v.x, v.y), pack_bf16x2(v.z, v.w));
    }
}

// ---------------- LayerNorm: warp per row, bf16 output ----------------
__global__ __launch_bounds__(256) void ln_kernel(const float* __restrict__ x,
                                                 const float* __restrict__ w,
                                                 const float* __restrict__ b,
                                                 uint32_t* __restrict__ out) {
    int row  = blockIdx.x * 8 + (threadIdx.x >> 5);
    int lane = threadIdx.x & 31;
    const float* xr = x + (size_t)row * DMODEL;
    float4 v[6];
    float s = 0.f, ss = 0.f;
#pragma unroll
    for (int i = 0; i < 6; i++) {
        v[i] = *(const float4*)(xr + lane * 4 + i * 128);
        s  += v[i].x + v[i].y + v[i].z + v[i].w;
        ss += v[i].x * v[i].x + v[i].y * v[i].y + v[i].z * v[i].z + v[i].w * v[i].w;
    }
#pragma unroll
    for (int off = 16; off; off >>= 1) {
        s  += __shfl_xor_sync(0xffffffffu, s, off);
        ss += __shfl_xor_sync(0xffffffffu, ss, off);
    }
    float mu  = s * (1.f / DMODEL);
    float var = ss * (1.f / DMODEL) - mu * mu;
    float rstd = rsqrtf(var + 1e-6f);
    uint32_t* orow = out + (size_t)row * 384;
#pragma unroll
    for (int i = 0; i < 6; i++) {
        int c = lane * 4 + i * 128;
        float4 wv = *(const float4*)(w + c);
        float4 bv = *(const float4*)(b + c);
        float o0 = (v[i].x - mu) * rstd * wv.x + bv.x;
        float o1 = (v[i].y - mu) * rstd * wv.y + bv.y;
        float o2 = (v[i].z - mu) * rstd * wv.z + bv.z;
        float o3 = (v[i].w - mu) * rstd * wv.w + bv.w;
        *(uint2*)(orow + lane * 2 + i * 64) =
            make_uint2(pack_bf16x2(o0, o1), pack_bf16x2(o2, o3));
    }
}

// ---------------- BF16 GEMM: cp.async 3-stage, scalar-LDS frags (R13-proven) ----
#define SKB 36
#define STG_U (128 * SKB)
#define STAGE_U (2 * STG_U)
#define G_SMEM_BYTES (3 * STAGE_U * 4)

template <int EPI>
__global__ __launch_bounds__(256, 2)
void gemm_bf16(const uint32_t* __restrict__ A, const uint32_t* __restrict__ B,
               const float* __restrict__ bias, void* __restrict__ Cout,
               int K, int N, const float* __restrict__ res, const float* __restrict__ gamma) {
    extern __shared__ uint32_t gsm[];
    uint32_t sbase = smem_u32(gsm);

    int tid = threadIdx.x, wid = tid >> 5, lane = tid & 31;
    int g = lane >> 2, t4 = lane & 3;
    int mw = (wid & 1) * 64;
    int nw = (wid >> 1) * 32;
    int bm = blockIdx.x * 128, bn = blockIdx.y * 128;

    float acc[4][4][4];
#pragma unroll
    for (int i = 0; i < 4; i++)
#pragma unroll
        for (int j = 0; j < 4; j++)
#pragma unroll
            for (int q = 0; q < 4; q++) acc[i][j][q] = 0.f;

    int K2 = K >> 1;
    const uint32_t* Ap[4];
    const uint32_t* Bp[4];
    uint32_t sdA[4];
#pragma unroll
    for (int j = 0; j < 4; j++) {
        int fi = tid + 256 * j;
        int row = fi >> 3, ch = fi & 7;
        Ap[j] = A + (size_t)(bm + row) * K2 + ch * 4;
        Bp[j] = B + (size_t)(bn + row) * K2 + ch * 4;
        sdA[j] = (row * SKB + ch * 4) * 4;
    }

    int NC = K >> 6;
#pragma unroll
    for (int st = 0; st < 2; st++) {
#pragma unroll
        for (int j = 0; j < 4; j++) {
            CP16(sbase + st * (STAGE_U * 4) + sdA[j], Ap[j] + st * 32);
            CP16(sbase + st * (STAGE_U * 4) + STG_U * 4 + sdA[j], Bp[j] + st * 32);
        }
        CP_COMMIT();
    }

    for (int c = 0; c < NC; c++) {
        if (c < NC - 1) CP_WAIT1(); else CP_WAIT0();
        __syncthreads();
        if (c + 2 < NC) {
            int st = (c + 2) % 3;
#pragma unroll
            for (int j = 0; j < 4; j++) {
                CP16(sbase + st * (STAGE_U * 4) + sdA[j], Ap[j] + (c + 2) * 32);
                CP16(sbase + st * (STAGE_U * 4) + STG_U * 4 + sdA[j], Bp[j] + (c + 2) * 32);
            }
            CP_COMMIT();
        }
        const uint32_t* As = gsm + (c % 3) * STAGE_U;
        const uint32_t* Bs = As + STG_U;
#pragma unroll
        for (int s = 0; s < 4; s++) {
            int kk = t4 + 8 * s;
            uint32_t af[4][4], bf[4][2];
#pragma unroll
            for (int mt = 0; mt < 4; mt++) {
                int r0 = (mw + mt * 16 + g) * SKB;
                int r1 = r0 + 8 * SKB;
                af[mt][0] = As[r0 + kk];
                af[mt][1] = As[r1 + kk];
                af[mt][2] = As[r0 + kk + 4];
                af[mt][3] = As[r1 + kk + 4];
            }
#pragma unroll
            for (int nt = 0; nt < 4; nt++) {
                int rb = (nw + nt * 8 + g) * SKB;
                bf[nt][0] = Bs[rb + kk];
                bf[nt][1] = Bs[rb + kk + 4];
            }
#pragma unroll
            for (int mt = 0; mt < 4; mt++)
#pragma unroll
                for (int nt = 0; nt < 4; nt++)
                    MMA_BF16(acc[mt][nt][0], acc[mt][nt][1], acc[mt][nt][2], acc[mt][nt][3],
                             af[mt][0], af[mt][1], af[mt][2], af[mt][3], bf[nt][0], bf[nt][1]);
        }
    }

#pragma unroll
    for (int mt = 0; mt < 4; mt++) {
#pragma unroll
        for (int half = 0; half < 2; half++) {
            int r = bm + mw + mt * 16 + g + half * 8;
            const float* resr = (EPI == 2) ? res + (size_t)r * N : nullptr;
#pragma unroll
            for (int nt = 0; nt < 4; nt++) {
                int cn = bn + nw + nt * 8 + 2 * t4;
                float v0 = acc[mt][nt][half * 2 + 0] + bias[cn];
                float v1 = acc[mt][nt][half * 2 + 1] + bias[cn + 1];
                if (EPI == 1) {
                    v0 = 0.5f * v0 * (1.f + erff(v0 * 0.70710678118654752f));
                    v1 = 0.5f * v1 * (1.f + erff(v1 * 0.70710678118654752f));
                    ((uint32_t*)Cout)[(size_t)r * (N >> 1) + (cn >> 1)] = pack_bf16x2(v0, v1);
                } else if (EPI == 2) {
                    v0 = resr[cn] + gamma[cn] * v0;
                    v1 = resr[cn + 1] + gamma[cn + 1] * v1;
                    *(float2*)((float*)Cout + (size_t)r * N + cn) = make_float2(v0, v1);
                } else {
                    *(float2*)((float*)Cout + (size_t)r * N + cn) = make_float2(v0, v1);
                }
            }
        }
    }
}

// ---------------- Flash attention v6: q-tile 64, 128 threads, high occupancy ----
#define KST 36
#define VOFF (64 * KST)
#define ABUF (VOFF + 64 * KST + 32)
__device__ __forceinline__ int vrow(int d) { return d * KST + ((d >> 4) << 3); }

__global__ __launch_bounds__(128) void attn_mma2(const float* __restrict__ qkv,
                                                 uint32_t* __restrict__ outb) {
    __shared__ uint32_t sm[ABUF];

    int bx = blockIdx.x, h = blockIdx.y;
    int s = 0;
#pragma unroll
    for (int i = 1; i < 8; i++) s += (bx >= c_pfx64[i]) ? 1 : 0;
    int q0   = (bx - c_pfx64[s]) * 64;
    int base = c_cu[s];
    int L    = c_cu[s + 1] - base;

    int tid = threadIdx.x, wid = tid >> 5, lane = tid & 31;
    int g = lane >> 2, t4 = lane & 3;
    int ltok = tid >> 1;             // 0..63: kv token row
    int dg   = (tid & 1) << 5;       // 0 or 32: d-range handled by this thread

    // ---- preload Q fragments (bf16, scaled by log2e/8) ----
    const float QSC = 0.18033688011112042f;
    uint32_t qa[4][4];
    {
        int r0 = q0 + wid * 16 + g, r1 = r0 + 8;
        bool v0 = r0 < L, v1 = r1 < L;
        const float* p0 = qkv + (size_t)(base + (v0 ? r0 : 0)) * 2304 + h * 64;
        const float* p1 = qkv + (size_t)(base + (v1 ? r1 : 0)) * 2304 + h * 64;
#pragma unroll
        for (int st = 0; st < 4; st++) {
            int k0 = 16 * st + 2 * t4, k1 = k0 + 8;
            qa[st][0] = v0 ? pack_bf16x2(p0[k0] * QSC, p0[k0 + 1] * QSC) : 0u;
            qa[st][1] = v1 ? pack_bf16x2(p1[k0] * QSC, p1[k0 + 1] * QSC) : 0u;
            qa[st][2] = v0 ? pack_bf16x2(p0[k1] * QSC, p0[k1 + 1] * QSC) : 0u;
            qa[st][3] = v1 ? pack_bf16x2(p1[k1] * QSC, p1[k1 + 1] * QSC) : 0u;
        }
    }

    float l0 = 0.f, l1 = 0.f;
    float acco[8][4];
#pragma unroll
    for (int nt = 0; nt < 8; nt++)
#pragma unroll
        for (int q = 0; q < 4; q++) acco[nt][q] = 0.f;

    int nkt = (L + 63) >> 6;

    for (int kt = 0; kt < nkt; kt++) {
        int kb = kt << 6;
        __syncthreads();
        // ---- load K/V tile into smem (this thread: token ltok, dims dg..dg+31) ----
        {
            int r = kb + ltok;
            bool kvalid = r < L;
            const float* kp = qkv + (size_t)(base + (kvalid ? r : 0)) * 2304 + 768 + h * 64 + dg;
            uint32_t kb2 = ltok * KST + (dg >> 1);
            uint16_t* Vh = (uint16_t*)(sm + VOFF);
#pragma unroll
            for (int half = 0; half < 2; half++) {
                float4 a0 = kvalid ? *(const float4*)(kp + half * 16)      : make_float4(0, 0, 0, 0);
                float4 a1 = kvalid ? *(const float4*)(kp + half * 16 + 4)  : make_float4(0, 0, 0, 0);
                float4 a2 = kvalid ? *(const float4*)(kp + half * 16 + 8)  : make_float4(0, 0, 0, 0);
                float4 a3 = kvalid ? *(const float4*)(kp + half * 16 + 12) : make_float4(0, 0, 0, 0);
                *(uint4*)&sm[kb2 + half * 8] =
                    make_uint4(pack_bf16x2(a0.x, a0.y), pack_bf16x2(a0.z, a0.w),
                               pack_bf16x2(a1.x, a1.y), pack_bf16x2(a1.z, a1.w));
                *(uint4*)&sm[kb2 + half * 8 + 4] =
                    make_uint4(pack_bf16x2(a2.x, a2.y), pack_bf16x2(a2.z, a2.w),
                               pack_bf16x2(a3.x, a3.y), pack_bf16x2(a3.z, a3.w));
            }
            const float* vp = kp + 768;
#pragma unroll
            for (int j = 0; j < 8; j++) {
                float4 v = kvalid ? *(const float4*)(vp + j * 4) : make_float4(0, 0, 0, 0);
                Vh[vrow(dg + 4 * j + 0) * 2 + ltok] = f2bf16(v.x);
                Vh[vrow(dg + 4 * j + 1) * 2 + ltok] = f2bf16(v.y);
                Vh[vrow(dg + 4 * j + 2) * 2 + ltok] = f2bf16(v.z);
                Vh[vrow(dg + 4 * j + 3) * 2 + ltok] = f2bf16(v.w);
            }
        }
        __syncthreads();

        // ---- S = Q K^T ----
        float sc[8][4];
#pragma unroll
        for (int nt = 0; nt < 8; nt++) {
            sc[nt][0] = 0.f; sc[nt][1] = 0.f; sc[nt][2] = 0.f; sc[nt][3] = 0.f;
        }
#pragma unroll
        for (int st = 0; st < 4; st++) {
            int kk = t4 + 8 * st;
#pragma unroll
            for (int nt = 0; nt < 8; nt++) {
                int rb = (nt * 8 + g) * KST;
                MMA_BF16(sc[nt][0], sc[nt][1], sc[nt][2], sc[nt][3],
                         qa[st][0], qa[st][1], qa[st][2], qa[st][3],
                         sm[rb + kk], sm[rb + kk + 4]);
            }
        }

        // ---- mask + fixed-max softmax (exp2 domain) ----
        if (kb + 64 > L) {
#pragma unroll
            for (int nt = 0; nt < 8; nt++) {
                int col = kb + nt * 8 + 2 * t4;
                if (col >= L)     { sc[nt][0] = -126.f; sc[nt][2] = -126.f; }
                if (col + 1 >= L) { sc[nt][1] = -126.f; sc[nt][3] = -126.f; }
            }
        }
#pragma unroll
        for (int nt = 0; nt < 8; nt++) {
            float p0 = fexp2nc(sc[nt][0]);
            float p1 = fexp2nc(sc[nt][1]);
            float p2 = fexp2nc(sc[nt][2]);
            float p3 = fexp2nc(sc[nt][3]);
            l0 += p0 + p1; l1 += p2 + p3;
            sc[nt][0] = p0; sc[nt][1] = p1; sc[nt][2] = p2; sc[nt][3] = p3;
        }

        // ---- O += P V ----
        const uint32_t* Vb = sm + VOFF;
#pragma unroll
        for (int st = 0; st < 4; st++) {
            uint32_t pa0 = pack_bf16x2(sc[2 * st][0], sc[2 * st][1]);
            uint32_t pa1 = pack_bf16x2(sc[2 * st][2], sc[2 * st][3]);
            uint32_t pa2 = pack_bf16x2(sc[2 * st + 1][0], sc[2 * st + 1][1]);
            uint32_t pa3 = pack_bf16x2(sc[2 * st + 1][2], sc[2 * st + 1][3]);
            int kk = 8 * st + t4;
#pragma unroll
            for (int nt = 0; nt < 8; nt++) {
                int rb = vrow(nt * 8 + g);
                MMA_BF16(acco[nt][0], acco[nt][1], acco[nt][2], acco[nt][3],
                         pa0, pa1, pa2, pa3, Vb[rb + kk], Vb[rb + kk + 4]);
            }
        }
    }

    // ---- final row-sum reduction + write O (bf16) ----
#pragma unroll
    for (int off = 1; off <= 2; off <<= 1) {
        l0 += __shfl_xor_sync(0xffffffffu, l0, off);
        l1 += __shfl_xor_sync(0xffffffffu, l1, off);
    }
    float inv0 = 1.f / l0, inv1 = 1.f / l1;
    int r0 = q0 + wid * 16 + g, r1 = r0 + 8;
#pragma unroll
    for (int nt = 0; nt < 8; nt++) {
        int col = h * 64 + nt * 8 + 2 * t4;
        if (r0 < L)
            outb[(size_t)(base + r0) * 384 + (col >> 1)] =
                pack_bf16x2(acco[nt][0] * inv0, acco[nt][1] * inv0);
        if (r1 < L)
            outb[(size_t)(base + r1) * 384 + (col >> 1)] =
                pack_bf16x2(acco[nt][2] * inv1, acco[nt][3] * inv1);
    }
}

// ---------------- launch ----------------
extern "C" void kernel_launch(void* const* d_in, const int* in_sizes, int n_in,
                              void* d_out, int out_size) {
    const float* x      = (const float*)d_in[0];
    const float* n1w    = (const float*)d_in[1];
    const float* n1b    = (const float*)d_in[2];
    const float* qkv_w  = (const float*)d_in[3];
    const float* qkv_b  = (const float*)d_in[4];
    const float* proj_w = (const float*)d_in[5];
    const float* proj_b = (const float*)d_in[6];
    const float* ls1    = (const float*)d_in[7];
    const float* n2w    = (const float*)d_in[8];
    const float* n2b    = (const float*)d_in[9];
    const float* fc1_w  = (const float*)d_in[10];
    const float* fc1_b  = (const float*)d_in[11];
    const float* fc2_w  = (const float*)d_in[12];
    const float* fc2_b  = (const float*)d_in[13];
    const float* ls2    = (const float*)d_in[14];
    float* out = (float*)d_out;

    uint32_t *xnb, *attnb, *hb, *wq, *wp, *w1, *w2;
    float *qkvf, *x1;
    cudaGetSymbolAddress((void**)&xnb,   g_xnb);
    cudaGetSymbolAddress((void**)&qkvf,  g_qkv);
    cudaGetSymbolAddress((void**)&attnb, g_attnb);
    cudaGetSymbolAddress((void**)&x1,    g_x1);
    cudaGetSymbolAddress((void**)&hb,    g_hb);
    cudaGetSymbolAddress((void**)&wq,    g_wq);
    cudaGetSymbolAddress((void**)&wp,    g_wp);
    cudaGetSymbolAddress((void**)&w1,    g_w1);
    cudaGetSymbolAddress((void**)&w2,    g_w2);

    cudaFuncSetAttribute(gemm_bf16<0>, cudaFuncAttributeMaxDynamicSharedMemorySize, G_SMEM_BYTES);
    cudaFuncSetAttribute(gemm_bf16<1>, cudaFuncAttributeMaxDynamicSharedMemorySize, G_SMEM_BYTES);
    cudaFuncSetAttribute(gemm_bf16<2>, cudaFuncAttributeMaxDynamicSharedMemorySize, G_SMEM_BYTES);

    cvt_bf16<<<1728, 256>>>(qkv_w, wq, 442368);
    cvt_bf16<<<576, 256>>>(proj_w, wp, 147456);
    ln_kernel<<<576, 256>>>(x, n1w, n1b, xnb);
    gemm_bf16<0><<<dim3(36, 18), 256, G_SMEM_BYTES>>>(xnb, wq, qkv_b, qkvf, 768, 2304, nullptr, nullptr);
    attn_mma2<<<dim3(72, 12), 128>>>(qkvf, attnb);
    gemm_bf16<2><<<dim3(36, 6), 256, G_SMEM_BYTES>>>(attnb, wp, proj_b, x1, 768, 768, x, ls1);
    cvt_bf16<<<2304, 256>>>(fc1_w, w1, 589824);
    cvt_bf16<<<2304, 256>>>(fc2_w, w2, 589824);
    ln_kernel<<<576, 256>>>(x1, n2w, n2b, xnb);
    gemm_bf16<1><<<dim3(36, 24), 256, G_SMEM_BYTES>>>(xnb, w1, fc1_b, hb, 768, 3072, nullptr, nullptr);
    gemm_bf16<2><<<dim3(36, 6), 256, G_SMEM_BYTES>>>(hb, w2, fc2_b, out, 3072, 768, x1, ls2);
}

// round 16
// speedup vs baseline: 1.1986x; 1.1986x over previous
#include <cuda_runtime.h>
#include <math.h>
#include <cstdint>

#define TOTAL 4608
#define DMODEL 768
#define DFF 3072

// -------- scratch --------
__device__ uint32_t g_xnb  [TOTAL * 384];
__device__ uint32_t g_qkvb [TOTAL * 1152];   // bf16x2 qkv (Q pre-scaled by log2e/8)
__device__ uint32_t g_attnb[TOTAL * 384];
__device__ float    g_x1   [TOTAL * 768];
__device__ uint32_t g_hb   [TOTAL * 1536];
__device__ uint32_t g_wq   [884736];
__device__ uint32_t g_wp   [294912];
__device__ uint32_t g_w1   [1179648];
__device__ uint32_t g_w2   [1179648];

__constant__ int c_cu[9]     = {0, 1024, 1920, 2688, 3328, 3840, 4288, 4544, 4608};
__constant__ int c_pfx128[9] = {0, 8, 15, 21, 26, 30, 34, 36, 37};

#define QSCALE 0.18033688011112042f   // log2(e)/8

__device__ __forceinline__ uint32_t smem_u32(const void* p) {
    uint32_t a;
    asm("{ .reg .u64 t; cvta.to.shared.u64 t, %1; cvt.u32.u64 %0, t; }" : "=r"(a) : "l"(p));
    return a;
}
__device__ __forceinline__ uint32_t pack_bf16x2(float lo, float hi) {
    uint32_t u;
    asm("cvt.rn.bf16x2.f32 %0, %1, %2;" : "=r"(u) : "f"(hi), "f"(lo));
    return u;
}
__device__ __forceinline__ float fexp2nc(float t) {
    float n = rintf(t);
    float f = t - n;
    float p = 8.98934e-3f;
    p = fmaf(p, f, 5.58263e-2f);
    p = fmaf(p, f, 2.40153e-1f);
    p = fmaf(p, f, 6.93147e-1f);
    p = fmaf(p, f, 1.0f);
    return __int_as_float(__float_as_int(p) + (((int)n) << 23));
}

#define MMA_BF16(d0,d1,d2,d3,a0,a1,a2,a3,b0,b1) \
    asm volatile("mma.sync.aligned.m16n8k16.row.col.f32.bf16.bf16.f32 " \
        "{%0,%1,%2,%3}, {%4,%5,%6,%7}, {%8,%9}, {%0,%1,%2,%3};" \
        : "+f"(d0), "+f"(d1), "+f"(d2), "+f"(d3) \
        : "r"(a0), "r"(a1), "r"(a2), "r"(a3), "r"(b0), "r"(b1))

#define CP16(dst, src) \
    asm volatile("cp.async.cg.shared.global [%0], [%1], 16;" :: "r"(dst), "l"(src))
#define CP_COMMIT() asm volatile("cp.async.commit_group;" ::: "memory")
#define CP_WAIT1()  asm volatile("cp.async.wait_group 1;" ::: "memory")
#define CP_WAIT0()  asm volatile("cp.async.wait_group 0;" ::: "memory")

// ---------------- f32 -> bf16x2 convert ----------------
__global__ __launch_bounds__(256) void cvt_bf16(const float* __restrict__ src,
                                                uint32_t* __restrict__ dst, int n4) {
    int i = blockIdx.x * 256 + threadIdx.x;
    if (i < n4) {
        float4 v = ((const float4*)src)[i];
        ((uint2*)dst)[i] = make_uint2(pack_bf16x2(v.x, v.y), pack_bf16x2(v.z, v.w));
    }
}

// ---------------- LayerNorm: warp per row, bf16 output ----------------
__global__ __launch_bounds__(256) void ln_kernel(const float* __restrict__ x,
                                                 const float* __restrict__ w,
                                                 const float* __restrict__ b,
                                                 uint32_t* __restrict__ out) {
    int row  = blockIdx.x * 8 + (threadIdx.x >> 5);
    int lane = threadIdx.x & 31;
    const float* xr = x + (size_t)row * DMODEL;
    float4 v[6];
    float s = 0.f, ss = 0.f;
#pragma unroll
    for (int i = 0; i < 6; i++) {
        v[i] = *(const float4*)(xr + lane * 4 + i * 128);
        s  += v[i].x + v[i].y + v[i].z + v[i].w;
        ss += v[i].x * v[i].x + v[i].y * v[i].y + v[i].z * v[i].z + v[i].w * v[i].w;
    }
#pragma unroll
    for (int off = 16; off; off >>= 1) {
        s  += __shfl_xor_sync(0xffffffffu, s, off);
        ss += __shfl_xor_sync(0xffffffffu, ss, off);
    }
    float mu  = s * (1.f / DMODEL);
    float var = ss * (1.f / DMODEL) - mu * mu;
    float rstd = rsqrtf(var + 1e-6f);
    uint32_t* orow = out + (size_t)row * 384;
#pragma unroll
    for (int i = 0; i < 6; i++) {
        int c = lane * 4 + i * 128;
        float4 wv = *(const float4*)(w + c);
        float4 bv = *(const float4*)(b + c);
        float o0 = (v[i].x - mu) * rstd * wv.x + bv.x;
        float o1 = (v[i].y - mu) * rstd * wv.y + bv.y;
        float o2 = (v[i].z - mu) * rstd * wv.z + bv.z;
        float o3 = (v[i].w - mu) * rstd * wv.w + bv.w;
        *(uint2*)(orow + lane * 2 + i * 64) =
            make_uint2(pack_bf16x2(o0, o1), pack_bf16x2(o2, o3));
    }
}

// ---------------- BF16 GEMM: cp.async 3-stage (R13-proven) ----------------
// EPI 0: +bias->f32  1: +bias,GELU->bf16  2: res+gamma*(acc+bias)->f32
// EPI 3: +bias, Q-cols (cn<768) scaled by QSCALE -> bf16
#define SKB 36
#define STG_U (128 * SKB)
#define STAGE_U (2 * STG_U)
#define G_SMEM_BYTES (3 * STAGE_U * 4)

template <int EPI>
__global__ __launch_bounds__(256, 2)
void gemm_bf16(const uint32_t* __restrict__ A, const uint32_t* __restrict__ B,
               const float* __restrict__ bias, void* __restrict__ Cout,
               int K, int N, const float* __restrict__ res, const float* __restrict__ gamma) {
    extern __shared__ uint32_t gsm[];
    uint32_t sbase = smem_u32(gsm);

    int tid = threadIdx.x, wid = tid >> 5, lane = tid & 31;
    int g = lane >> 2, t4 = lane & 3;
    int mw = (wid & 1) * 64;
    int nw = (wid >> 1) * 32;
    int bm = blockIdx.x * 128, bn = blockIdx.y * 128;

    float acc[4][4][4];
#pragma unroll
    for (int i = 0; i < 4; i++)
#pragma unroll
        for (int j = 0; j < 4; j++)
#pragma unroll
            for (int q = 0; q < 4; q++) acc[i][j][q] = 0.f;

    int K2 = K >> 1;
    const uint32_t* Ap[4];
    const uint32_t* Bp[4];
    uint32_t sdA[4];
#pragma unroll
    for (int j = 0; j < 4; j++) {
        int fi = tid + 256 * j;
        int row = fi >> 3, ch = fi & 7;
        Ap[j] = A + (size_t)(bm + row) * K2 + ch * 4;
        Bp[j] = B + (size_t)(bn + row) * K2 + ch * 4;
        sdA[j] = (row * SKB + ch * 4) * 4;
    }

    int NC = K >> 6;
#pragma unroll
    for (int st = 0; st < 2; st++) {
#pragma unroll
        for (int j = 0; j < 4; j++) {
            CP16(sbase + st * (STAGE_U * 4) + sdA[j], Ap[j] + st * 32);
            CP16(sbase + st * (STAGE_U * 4) + STG_U * 4 + sdA[j], Bp[j] + st * 32);
        }
        CP_COMMIT();
    }

    for (int c = 0; c < NC; c++) {
        if (c < NC - 1) CP_WAIT1(); else CP_WAIT0();
        __syncthreads();
        if (c + 2 < NC) {
            int st = (c + 2) % 3;
#pragma unroll
            for (int j = 0; j < 4; j++) {
                CP16(sbase + st * (STAGE_U * 4) + sdA[j], Ap[j] + (c + 2) * 32);
                CP16(sbase + st * (STAGE_U * 4) + STG_U * 4 + sdA[j], Bp[j] + (c + 2) * 32);
            }
            CP_COMMIT();
        }
        const uint32_t* As = gsm + (c % 3) * STAGE_U;
        const uint32_t* Bs = As + STG_U;
#pragma unroll
        for (int s = 0; s < 4; s++) {
            int kk = t4 + 8 * s;
            uint32_t af[4][4], bf[4][2];
#pragma unroll
            for (int mt = 0; mt < 4; mt++) {
                int r0 = (mw + mt * 16 + g) * SKB;
                int r1 = r0 + 8 * SKB;
                af[mt][0] = As[r0 + kk];
                af[mt][1] = As[r1 + kk];
                af[mt][2] = As[r0 + kk + 4];
                af[mt][3] = As[r1 + kk + 4];
            }
#pragma unroll
            for (int nt = 0; nt < 4; nt++) {
                int rb = (nw + nt * 8 + g) * SKB;
                bf[nt][0] = Bs[rb + kk];
                bf[nt][1] = Bs[rb + kk + 4];
            }
#pragma unroll
            for (int mt = 0; mt < 4; mt++)
#pragma unroll
                for (int nt = 0; nt < 4; nt++)
                    MMA_BF16(acc[mt][nt][0], acc[mt][nt][1], acc[mt][nt][2], acc[mt][nt][3],
                             af[mt][0], af[mt][1], af[mt][2], af[mt][3], bf[nt][0], bf[nt][1]);
        }
    }

#pragma unroll
    for (int mt = 0; mt < 4; mt++) {
#pragma unroll
        for (int half = 0; half < 2; half++) {
            int r = bm + mw + mt * 16 + g + half * 8;
            const float* resr = (EPI == 2) ? res + (size_t)r * N : nullptr;
#pragma unroll
            for (int nt = 0; nt < 4; nt++) {
                int cn = bn + nw + nt * 8 + 2 * t4;
                float v0 = acc[mt][nt][half * 2 + 0] + bias[cn];
                float v1 = acc[mt][nt][half * 2 + 1] + bias[cn + 1];
                if (EPI == 1) {
                    v0 = 0.5f * v0 * (1.f + erff(v0 * 0.70710678118654752f));
                    v1 = 0.5f * v1 * (1.f + erff(v1 * 0.70710678118654752f));
                    ((uint32_t*)Cout)[(size_t)r * (N >> 1) + (cn >> 1)] = pack_bf16x2(v0, v1);
                } else if (EPI == 2) {
                    v0 = resr[cn] + gamma[cn] * v0;
                    v1 = resr[cn + 1] + gamma[cn + 1] * v1;
                    *(float2*)((float*)Cout + (size_t)r * N + cn) = make_float2(v0, v1);
                } else if (EPI == 3) {
                    float scq = (cn < 768) ? QSCALE : 1.0f;
                    ((uint32_t*)Cout)[(size_t)r * (N >> 1) + (cn >> 1)] =
                        pack_bf16x2(v0 * scq, v1 * scq);
                } else {
                    *(float2*)((float*)Cout + (size_t)r * N + cn) = make_float2(v0, v1);
                }
            }
        }
    }
}

// ---------------- Flash attention v7: bf16 inputs, R13 structure ----------------
#define KST 36
#define VOFF (64 * KST)
#define ABUF (VOFF + 64 * KST + 32)
__device__ __forceinline__ int vrow(int d) { return d * KST + ((d >> 4) << 3); }

__global__ __launch_bounds__(256, 2) void attn_mma2(const uint32_t* __restrict__ qkvb,
                                                    uint32_t* __restrict__ outb) {
    __shared__ uint32_t sm[2 * ABUF];

    int bx = blockIdx.x, h = blockIdx.y;
    int s = 0;
#pragma unroll
    for (int i = 1; i < 8; i++) s += (bx >= c_pfx128[i]) ? 1 : 0;
    int q0   = (bx - c_pfx128[s]) * 128;
    int base = c_cu[s];
    int L    = c_cu[s + 1] - base;

    int tid = threadIdx.x, wid = tid >> 5, lane = tid & 31;
    int g = lane >> 2, t4 = lane & 3;
    int ltok = tid >> 2;
    int dg   = (tid & 3) << 4;          // d offset 0,16,32,48

    // ---- preload Q fragments (already bf16 + scaled in gmem) ----
    uint32_t qa[4][4];
    {
        int r0 = q0 + wid * 16 + g, r1 = r0 + 8;
        bool v0 = r0 < L, v1 = r1 < L;
        const uint32_t* p0 = qkvb + (size_t)(base + (v0 ? r0 : 0)) * 1152 + h * 32;
        const uint32_t* p1 = qkvb + (size_t)(base + (v1 ? r1 : 0)) * 1152 + h * 32;
#pragma unroll
        for (int st = 0; st < 4; st++) {
            int u0 = 8 * st + t4, u1 = u0 + 4;
            qa[st][0] = v0 ? p0[u0] : 0u;
            qa[st][1] = v1 ? p1[u0] : 0u;
            qa[st][2] = v0 ? p0[u1] : 0u;
            qa[st][3] = v1 ? p1[u1] : 0u;
        }
    }

    float l0 = 0.f, l1 = 0.f;
    float acco[8][4];
#pragma unroll
    for (int nt = 0; nt < 8; nt++)
#pragma unroll
        for (int q = 0; q < 4; q++) acco[nt][q] = 0.f;

    int nkt = (L + 63) >> 6;

    uint4 krr[2], vrr[2];
    {
        int r = ltok;
        bool kv = r < L;
        const uint32_t* kp = qkvb + (size_t)(base + (kv ? r : 0)) * 1152 + 384 + h * 32 + (dg >> 1);
        krr[0] = kv ? *(const uint4*)(kp)     : make_uint4(0, 0, 0, 0);
        krr[1] = kv ? *(const uint4*)(kp + 4) : make_uint4(0, 0, 0, 0);
        vrr[0] = kv ? *(const uint4*)(kp + 384)     : make_uint4(0, 0, 0, 0);
        vrr[1] = kv ? *(const uint4*)(kp + 388) : make_uint4(0, 0, 0, 0);
    }
    {
        uint32_t* Kb = sm;
        uint32_t kb2 = ltok * KST + (dg >> 1);
        *(uint4*)&Kb[kb2]     = krr[0];
        *(uint4*)&Kb[kb2 + 4] = krr[1];
        uint16_t* Vh = (uint16_t*)(Kb + VOFF);
#pragma unroll
        for (int j = 0; j < 8; j++) {
            uint32_t u = (j < 4) ? (&vrr[0].x)[j] : (&vrr[1].x)[j - 4];
            Vh[vrow(dg + 2 * j) * 2 + ltok]     = (uint16_t)(u & 0xffffu);
            Vh[vrow(dg + 2 * j + 1) * 2 + ltok] = (uint16_t)(u >> 16);
        }
    }

    for (int kt = 0; kt < nkt; kt++) {
        int kb = kt << 6;
        if (kt + 1 < nkt) {
            int r = kb + 64 + ltok;
            bool kv = r < L;
            const uint32_t* kp = qkvb + (size_t)(base + (kv ? r : 0)) * 1152 + 384 + h * 32 + (dg >> 1);
            krr[0] = kv ? *(const uint4*)(kp)     : make_uint4(0, 0, 0, 0);
            krr[1] = kv ? *(const uint4*)(kp + 4) : make_uint4(0, 0, 0, 0);
            vrr[0] = kv ? *(const uint4*)(kp + 384)     : make_uint4(0, 0, 0, 0);
            vrr[1] = kv ? *(const uint4*)(kp + 388) : make_uint4(0, 0, 0, 0);
        }
        __syncthreads();

        const uint32_t* Kb = sm + (kt & 1) * ABUF;
        const uint32_t* Vb = Kb + VOFF;

        // ---- S = Q K^T (log2 domain) ----
        float sc[8][4];
#pragma unroll
        for (int nt = 0; nt < 8; nt++) {
            sc[nt][0] = 0.f; sc[nt][1] = 0.f; sc[nt][2] = 0.f; sc[nt][3] = 0.f;
        }
#pragma unroll
        for (int st = 0; st < 4; st++) {
            int kk = t4 + 8 * st;
#pragma unroll
            for (int nt = 0; nt < 8; nt++) {
                int rb = (nt * 8 + g) * KST;
                MMA_BF16(sc[nt][0], sc[nt][1], sc[nt][2], sc[nt][3],
                         qa[st][0], qa[st][1], qa[st][2], qa[st][3],
                         Kb[rb + kk], Kb[rb + kk + 4]);
            }
        }

        // ---- STS next tile (overlaps softmax) ----
        if (kt + 1 < nkt) {
            uint32_t* Kn = sm + ((kt + 1) & 1) * ABUF;
            uint32_t kb2 = ltok * KST + (dg >> 1);
            *(uint4*)&Kn[kb2]     = krr[0];
            *(uint4*)&Kn[kb2 + 4] = krr[1];
            uint16_t* Vh = (uint16_t*)(Kn + VOFF);
#pragma unroll
            for (int j = 0; j < 8; j++) {
                uint32_t u = (j < 4) ? (&vrr[0].x)[j] : (&vrr[1].x)[j - 4];
                Vh[vrow(dg + 2 * j) * 2 + ltok]     = (uint16_t)(u & 0xffffu);
                Vh[vrow(dg + 2 * j + 1) * 2 + ltok] = (uint16_t)(u >> 16);
            }
        }

        // ---- mask + fixed-max softmax (exp2 domain) ----
        if (kb + 64 > L) {
#pragma unroll
            for (int nt = 0; nt < 8; nt++) {
                int col = kb + nt * 8 + 2 * t4;
                if (col >= L)     { sc[nt][0] = -126.f; sc[nt][2] = -126.f; }
                if (col + 1 >= L) { sc[nt][1] = -126.f; sc[nt][3] = -126.f; }
            }
        }
#pragma unroll
        for (int nt = 0; nt < 8; nt++) {
            float p0 = fexp2nc(sc[nt][0]);
            float p1 = fexp2nc(sc[nt][1]);
            float p2 = fexp2nc(sc[nt][2]);
            float p3 = fexp2nc(sc[nt][3]);
            l0 += p0 + p1; l1 += p2 + p3;
            sc[nt][0] = p0; sc[nt][1] = p1; sc[nt][2] = p2; sc[nt][3] = p3;
        }

        // ---- O += P V : P packs directly from accumulator layout ----
#pragma unroll
        for (int st = 0; st < 4; st++) {
            uint32_t pa0 = pack_bf16x2(sc[2 * st][0], sc[2 * st][1]);
            uint32_t pa1 = pack_bf16x2(sc[2 * st][2], sc[2 * st][3]);
            uint32_t pa2 = pack_bf16x2(sc[2 * st + 1][0], sc[2 * st + 1][1]);
            uint32_t pa3 = pack_bf16x2(sc[2 * st + 1][2], sc[2 * st + 1][3]);
            int kk = 8 * st + t4;
#pragma unroll
            for (int nt = 0; nt < 8; nt++) {
                int rb = vrow(nt * 8 + g);
                MMA_BF16(acco[nt][0], acco[nt][1], acco[nt][2], acco[nt][3],
                         pa0, pa1, pa2, pa3, Vb[rb + kk], Vb[rb + kk + 4]);
            }
        }
    }

    // ---- final row-sum reduction + write O (bf16) ----
#pragma unroll
    for (int off = 1; off <= 2; off <<= 1) {
        l0 += __shfl_xor_sync(0xffffffffu, l0, off);
        l1 += __shfl_xor_sync(0xffffffffu, l1, off);
    }
    float inv0 = 1.f / l0, inv1 = 1.f / l1;
    int r0 = q0 + wid * 16 + g, r1 = r0 + 8;
#pragma unroll
    for (int nt = 0; nt < 8; nt++) {
        int col = h * 64 + nt * 8 + 2 * t4;
        if (r0 < L)
            outb[(size_t)(base + r0) * 384 + (col >> 1)] =
                pack_bf16x2(acco[nt][0] * inv0, acco[nt][1] * inv0);
        if (r1 < L)
            outb[(size_t)(base + r1) * 384 + (col >> 1)] =
                pack_bf16x2(acco[nt][2] * inv1, acco[nt][3] * inv1);
    }
}

// ---------------- launch ----------------
extern "C" void kernel_launch(void* const* d_in, const int* in_sizes, int n_in,
                              void* d_out, int out_size) {
    const float* x      = (const float*)d_in[0];
    const float* n1w    = (const float*)d_in[1];
    const float* n1b    = (const float*)d_in[2];
    const float* qkv_w  = (const float*)d_in[3];
    const float* qkv_b  = (const float*)d_in[4];
    const float* proj_w = (const float*)d_in[5];
    const float* proj_b = (const float*)d_in[6];
    const float* ls1    = (const float*)d_in[7];
    const float* n2w    = (const float*)d_in[8];
    const float* n2b    = (const float*)d_in[9];
    const float* fc1_w  = (const float*)d_in[10];
    const float* fc1_b  = (const float*)d_in[11];
    const float* fc2_w  = (const float*)d_in[12];
    const float* fc2_b  = (const float*)d_in[13];
    const float* ls2    = (const float*)d_in[14];
    float* out = (float*)d_out;

    uint32_t *xnb, *qkvb, *attnb, *hb, *wq, *wp, *w1, *w2;
    float *x1;
    cudaGetSymbolAddress((void**)&xnb,   g_xnb);
    cudaGetSymbolAddress((void**)&qkvb,  g_qkvb);
    cudaGetSymbolAddress((void**)&attnb, g_attnb);
    cudaGetSymbolAddress((void**)&x1,    g_x1);
    cudaGetSymbolAddress((void**)&hb,    g_hb);
    cudaGetSymbolAddress((void**)&wq,    g_wq);
    cudaGetSymbolAddress((void**)&wp,    g_wp);
    cudaGetSymbolAddress((void**)&w1,    g_w1);
    cudaGetSymbolAddress((void**)&w2,    g_w2);

    cudaFuncSetAttribute(gemm_bf16<1>, cudaFuncAttributeMaxDynamicSharedMemorySize, G_SMEM_BYTES);
    cudaFuncSetAttribute(gemm_bf16<2>, cudaFuncAttributeMaxDynamicSharedMemorySize, G_SMEM_BYTES);
    cudaFuncSetAttribute(gemm_bf16<3>, cudaFuncAttributeMaxDynamicSharedMemorySize, G_SMEM_BYTES);

    cvt_bf16<<<1728, 256>>>(qkv_w, wq, 442368);
    cvt_bf16<<<576, 256>>>(proj_w, wp, 147456);
    ln_kernel<<<576, 256>>>(x, n1w, n1b, xnb);
    gemm_bf16<3><<<dim3(36, 18), 256, G_SMEM_BYTES>>>(xnb, wq, qkv_b, qkvb, 768, 2304, nullptr, nullptr);
    attn_mma2<<<dim3(37, 12), 256>>>(qkvb, attnb);
    gemm_bf16<2><<<dim3(36, 6), 256, G_SMEM_BYTES>>>(attnb, wp, proj_b, x1, 768, 768, x, ls1);
    cvt_bf16<<<2304, 256>>>(fc1_w, w1, 589824);
    cvt_bf16<<<2304, 256>>>(fc2_w, w2, 589824);
    ln_kernel<<<576, 256>>>(x1, n2w, n2b, xnb);
    gemm_bf16<1><<<dim3(36, 24), 256, G_SMEM_BYTES>>>(xnb, w1, fc1_b, hb, 768, 3072, nullptr, nullptr);
    gemm_bf16<2><<<dim3(36, 6), 256, G_SMEM_BYTES>>>(hb, w2, fc2_b, out, 3072, 768, x1, ls2);
}